// round 16
// baseline (speedup 1.0000x reference)
#include <cuda_runtime.h>
#include <cuda_bf16.h>
#include <math.h>
#include <stdint.h>

// ---------------------------------------------------------------------------
// GGNN forward. GEMMs on tensor cores via portable mma.sync (bf16, fp32 acc)
// with bf16x3 split emulation: C = Ah*Bh + Al*Bh + Ah*Bl  (residual ~2^-18).
// R15 changes (on the 2860us R12 baseline + merged CSR):
//   * BM 64 -> 128; warp tile m64 x n40 (4 m16 per warp): 60 MMA vs ~26 L1
//     ops per warp-ktile (2x MMA density; RAW distance 20) -> latency-bound
//     GEMM gets far more work per issued instruction
//   * A double-buffered at HALF-K granularity (128 x 80 fp32 chunks, 45KB,
//     352B rows) so the pipeline still fits beside resident W (198KB smem)
// ---------------------------------------------------------------------------

#define HD 150          // feature dim
#define LD 160          // padded activation leading dim (fp32)
#define NMAX 100000
#define EMAX 500000
#define GMAX 16
#define NMATS 10        // W1_0,W2_0,W1_1,W2_1, Wih x3, Whh x3

#define BM 128          // rows per m-tile
#define KTI 10          // k chunks of 16 (K=160, pads are zero)

// smem layout (bytes). W rows 336B (conflict-free ldmatrix).
// A chunk rows 352B (88 floats: conflict-free LDS.64 quads), 128 x 80 fp32.
#define WSTRIDE 336
#define ACH_FSTRIDE 88                 // floats per A-chunk row
#define O_WHI 0
#define O_WLO 53760                    // 160*336
#define O_A0  107520
#define A_CH  45056                    // 128*352
#define O_A1  152576
#define O_BIAS 197632
#define SMEM_TOTAL 198400

static constexpr size_t GS = (size_t)NMAX * LD;   // gate buffer stride

// ---- scratch (device globals, zero-initialized at module load) ----
__device__ float g_h  [NMAX * LD];
__device__ float g_t0 [NMAX * LD];
__device__ float g_t1 [NMAX * LD];
__device__ float g_z0 [NMAX * LD];
__device__ float g_z1 [NMAX * LD];
__device__ float g_inc[NMAX * LD];
__device__ float g_gate[6 * (size_t)NMAX * LD];   // ir,iz,in,hr,hz,hn
__device__ float g_graph[GMAX * HD];
__device__ __align__(16) __nv_bfloat16 g_Whi[NMATS * LD * LD];  // [mat][n][k]
__device__ __align__(16) __nv_bfloat16 g_Wlo[NMATS * LD * LD];

// CSR (rebuilt every launch; edges are static inputs)
__device__ int g_cnt [2][NMAX];
__device__ int g_off [2][NMAX + 1];
__device__ int g_cur [2][NMAX];
__device__ int g_srcs[2][EMAX];
__device__ int g_bsum[2][128];

// ---------------------------------------------------------------------------
// helpers
// ---------------------------------------------------------------------------
__device__ __forceinline__ uint32_t smem_u32(const void* p) {
    uint32_t a;
    asm("{ .reg .u64 t; cvta.to.shared.u64 t, %1; cvt.u32.u64 %0, t; }"
        : "=r"(a) : "l"(p));
    return a;
}
__device__ __forceinline__ void cp16(uint32_t dst, const void* src) {
    asm volatile("cp.async.cg.shared.global [%0], [%1], 16;"
                 :: "r"(dst), "l"(src));
}
#define CP_COMMIT() asm volatile("cp.async.commit_group;" ::: "memory")
#define CP_WAIT(n)  asm volatile("cp.async.wait_group %0;" :: "n"(n) : "memory")

__device__ __forceinline__ void ldmx2(uint32_t* r, uint32_t addr) {
    asm volatile("ldmatrix.sync.aligned.m8n8.x2.shared.b16 {%0,%1}, [%2];"
                 : "=r"(r[0]), "=r"(r[1]) : "r"(addr));
}
__device__ __forceinline__ void mma16816(float* c, const uint32_t* a,
                                         const uint32_t* b) {
    asm volatile("mma.sync.aligned.m16n8k16.row.col.f32.bf16.bf16.f32 "
                 "{%0,%1,%2,%3}, {%4,%5,%6,%7}, {%8,%9}, {%0,%1,%2,%3};"
                 : "+f"(c[0]), "+f"(c[1]), "+f"(c[2]), "+f"(c[3])
                 : "r"(a[0]), "r"(a[1]), "r"(a[2]), "r"(a[3]),
                   "r"(b[0]), "r"(b[1]));
}
__device__ __forceinline__ uint32_t f2bf2(float a, float b) {
    __nv_bfloat162 h = __floats2bfloat162_rn(a, b);
    return *reinterpret_cast<uint32_t*>(&h);
}
__device__ __forceinline__ uint32_t lo2(float2 v, uint32_t hi) {
    const float hx = __uint_as_float(hi << 16);
    const float hy = __uint_as_float(hi & 0xffff0000u);
    return f2bf2(v.x - hx, v.y - hy);
}

// ---------------------------------------------------------------------------
// Weight pre-split: 10 matrices -> [LD x LD] bf16 hi/lo in global.
// ---------------------------------------------------------------------------
__global__ void make_wsplit(const float* __restrict__ W1_0, const float* __restrict__ W2_0,
                            const float* __restrict__ W1_1, const float* __restrict__ W2_1,
                            const float* __restrict__ Wih,  const float* __restrict__ Whh)
{
    const int total = NMATS * LD * LD;
    for (int idx = blockIdx.x * blockDim.x + threadIdx.x; idx < total;
         idx += gridDim.x * blockDim.x) {
        const int mat = idx / (LD * LD);
        const int rem = idx - mat * (LD * LD);
        const int r = rem / LD;
        const int k = rem - r * LD;
        float v = 0.f;
        if (r < HD && k < HD) {
            if      (mat == 0) v = W1_0[r * HD + k];
            else if (mat == 1) v = W2_0[r * HD + k];
            else if (mat == 2) v = W1_1[r * HD + k];
            else if (mat == 3) v = W2_1[r * HD + k];
            else if (mat <= 6) v = Wih[((mat - 4) * HD + r) * HD + k];
            else               v = Whh[((mat - 7) * HD + r) * HD + k];
        }
        __nv_bfloat16 hi = __float2bfloat16_rn(v);
        __nv_bfloat16 lo = __float2bfloat16_rn(v - __bfloat162float(hi));
        g_Whi[idx] = hi;
        g_Wlo[idx] = lo;
    }
}

// ---------------------------------------------------------------------------
// Multi-matrix persistent tensor-core GEMM.
//   For each job m: C[m][M x 150(pad160)] = act(A[m] @ W[mat[m]].T + bias[m])
// 8 warps = 2m(64 rows) x 4n(40 cols). Each unit (128-row tile) is computed
// in 2 half-K steps; A chunks (128 x 80 fp32) double-buffer across steps.
// ---------------------------------------------------------------------------
struct Jobs {
    const float* A[6];
    float*       C[6];
    const float* bias[6];
    int          mat[6];
    int          nmats;
    int          act;
};

__device__ __forceinline__ void load_a_chunk(uint32_t dstBase,
                                             const float* __restrict__ A,
                                             int t, int h, int M, int tid)
{
    // 128 rows x 20 uint4 (80 floats) from columns [80h, 80h+80)
    for (int jj = tid; jj < 128 * 20; jj += 256) {
        const int r = jj / 20, u = jj - r * 20;
        const int grow = min(t * BM + r, M - 1);
        cp16(dstBase + r * 352 + u * 16,
             A + (size_t)grow * LD + h * 80 + u * 4);
    }
}

__global__ __launch_bounds__(256, 1)
void gemm_multi(Jobs j, int tiles, int M)
{
    extern __shared__ char smem[];
    const uint32_t sb = smem_u32(smem);
    const int tid  = threadIdx.x;
    const int wid  = tid >> 5;
    const int lane = tid & 31;
    const int warpM = wid & 1;          // m64 half of BM=128
    const int warpN = wid >> 1;         // n40 quarter

    const int units = j.nmats * tiles;
    const int u0 = (int)(((long long)units * blockIdx.x) / gridDim.x);
    const int u1 = (int)(((long long)units * (blockIdx.x + 1)) / gridDim.x);
    if (u0 >= u1) return;
    const int steps = 2 * (u1 - u0);

    // B ldmatrix.x2 addresses: 5 n8 tiles; lanes 0-7 rows@k0, 8-15 rows@k8
    const int rB2 = lane & 7;
    const int kB2 = ((lane >> 3) & 1) << 3;
    uint32_t bAddr[5];
    #pragma unroll
    for (int p = 0; p < 5; p++)
        bAddr[p] = sb + O_WHI + (warpN * 40 + p * 8 + rB2) * WSTRIDE + kB2 * 2;

    const int rowA = warpM * 64 + (lane >> 2);   // + mi*16
    const int kA   = (lane & 3) * 2;

    // ---- prologue: A chunk for step 0 into buf0 ----
    {
        const int m0 = u0 / tiles, t0 = u0 - m0 * tiles;
        load_a_chunk(sb + O_A0, j.A[m0], t0, 0, M, tid);
        CP_COMMIT();
    }

    float acc[4][5][4];
    int curMat = -1;

    for (int s = 0; s < steps; s++) {
        const int u = u0 + (s >> 1);
        const int h = s & 1;
        const int m = u / tiles;
        const int t = u - m * tiles;

        if (h == 0 && m != curMat) {       // (re)load W + bias for this job
            curMat = m;
            const int mat = j.mat[m];
            const __nv_bfloat16* Wh = g_Whi + (size_t)mat * LD * LD;
            const __nv_bfloat16* Wl = g_Wlo + (size_t)mat * LD * LD;
            for (int jj = tid; jj < 2 * LD * 20; jj += 256) {
                const int sp = (jj >= LD * 20);
                const int j2 = sp ? (jj - LD * 20) : jj;
                const int r  = j2 / 20;
                const int uu = j2 - r * 20;
                cp16(sb + (sp ? O_WLO : O_WHI) + r * WSTRIDE + uu * 16,
                     (sp ? Wl : Wh) + (size_t)r * LD + uu * 8);
            }
            CP_COMMIT();
            const float* bp = j.bias[m];
            for (int c = tid; c < LD; c += 256)
                *reinterpret_cast<float*>(smem + O_BIAS + c * 4) =
                    (c < HD) ? bp[c] : 0.f;
        }

        // ---- prefetch A chunk for step s+1 into the other buffer ----
        if (s + 1 < steps) {
            const int un = u0 + ((s + 1) >> 1);
            const int hn = (s + 1) & 1;
            const int mn = un / tiles;
            const int tn = un - mn * tiles;
            load_a_chunk(sb + ((s & 1) ? O_A0 : O_A1), j.A[mn], tn, hn, M, tid);
            CP_COMMIT();
            CP_WAIT(1);    // current chunk (+ any W) done; next may be in flight
        } else {
            CP_WAIT(0);
        }
        __syncthreads();

        const float* sA = reinterpret_cast<const float*>(
            smem + ((s & 1) ? O_A1 : O_A0));

        if (h == 0) {
            #pragma unroll
            for (int mi = 0; mi < 4; mi++)
                #pragma unroll
                for (int p = 0; p < 5; p++)
                    #pragma unroll
                    for (int q = 0; q < 4; q++) acc[mi][p][q] = 0.f;
        }

        #pragma unroll
        for (int ktl = 0; ktl < 5; ktl++) {
            const int kt = h * 5 + ktl;         // global k-tile for B
            // A fragments for the four m16 tiles, split to bf16 hi/lo
            uint32_t ah[4][4], al[4][4];
            #pragma unroll
            for (int mi = 0; mi < 4; mi++) {
                const float* ap = sA + (rowA + mi * 16) * ACH_FSTRIDE
                                     + ktl * 16 + kA;
                const float2 v00 = *reinterpret_cast<const float2*>(ap);
                const float2 v10 = *reinterpret_cast<const float2*>(ap + 8 * ACH_FSTRIDE);
                const float2 v01 = *reinterpret_cast<const float2*>(ap + 8);
                const float2 v11 = *reinterpret_cast<const float2*>(ap + 8 * ACH_FSTRIDE + 8);
                ah[mi][0] = f2bf2(v00.x, v00.y);  al[mi][0] = lo2(v00, ah[mi][0]);
                ah[mi][1] = f2bf2(v10.x, v10.y);  al[mi][1] = lo2(v10, ah[mi][1]);
                ah[mi][2] = f2bf2(v01.x, v01.y);  al[mi][2] = lo2(v01, ah[mi][2]);
                ah[mi][3] = f2bf2(v11.x, v11.y);  al[mi][3] = lo2(v11, ah[mi][3]);
            }

            // product-major: 20 independent MMAs between accumulator reuses;
            // each B fragment feeds all four m16 tiles (4x reuse).
            uint32_t bfr[5][2];
            #pragma unroll
            for (int p = 0; p < 5; p++) ldmx2(bfr[p], bAddr[p] + kt * 32);
            #pragma unroll
            for (int p = 0; p < 5; p++)
                #pragma unroll
                for (int mi = 0; mi < 4; mi++)
                    mma16816(acc[mi][p], ah[mi], bfr[p]);
            #pragma unroll
            for (int p = 0; p < 5; p++)
                #pragma unroll
                for (int mi = 0; mi < 4; mi++)
                    mma16816(acc[mi][p], al[mi], bfr[p]);
            #pragma unroll
            for (int p = 0; p < 5; p++)
                ldmx2(bfr[p], bAddr[p] + kt * 32 + (O_WLO - O_WHI));
            #pragma unroll
            for (int p = 0; p < 5; p++)
                #pragma unroll
                for (int mi = 0; mi < 4; mi++)
                    mma16816(acc[mi][p], ah[mi], bfr[p]);
        }

        // ---- epilogue after second half: bias + act, write fp32 ----
        if (h == 1) {
            float* Cp = j.C[m];
            #pragma unroll
            for (int mi = 0; mi < 4; mi++) {
                const int r0 = t * BM + warpM * 64 + mi * 16 + (lane >> 2);
                #pragma unroll
                for (int p = 0; p < 5; p++) {
                    const int c0 = warpN * 40 + p * 8 + (lane & 3) * 2;
                    const float b0 = *reinterpret_cast<float*>(smem + O_BIAS + c0 * 4);
                    const float b1 = *reinterpret_cast<float*>(smem + O_BIAS + (c0 + 1) * 4);
                    float x0 = acc[mi][p][0] + b0, x1 = acc[mi][p][1] + b1;
                    float x2 = acc[mi][p][2] + b0, x3 = acc[mi][p][3] + b1;
                    if (j.act) {
                        x0 = x0 > 0.f ? x0 : 0.01f * x0;
                        x1 = x1 > 0.f ? x1 : 0.01f * x1;
                        x2 = x2 > 0.f ? x2 : 0.01f * x2;
                        x3 = x3 > 0.f ? x3 : 0.01f * x3;
                    }
                    if (r0 < M)
                        *reinterpret_cast<float2*>(Cp + (size_t)r0 * LD + c0) =
                            make_float2(x0, x1);
                    if (r0 + 8 < M)
                        *reinterpret_cast<float2*>(Cp + (size_t)(r0 + 8) * LD + c0) =
                            make_float2(x2, x3);
                }
            }
        }
        __syncthreads();   // protect A/W/bias buffers before next step
    }
}

// ---------------------------------------------------------------------------
// CSR build (merged, 6 launches). counts -> offsets -> cursors -> fill.
// ---------------------------------------------------------------------------
#define SCAN_BLK 1024
#define SCAN_NB  ((NMAX + SCAN_BLK - 1) / SCAN_BLK)   // 98

__global__ void csr_zero()
{
    int* c = &g_cnt[0][0];
    for (int i = blockIdx.x * blockDim.x + threadIdx.x; i < 2 * NMAX;
         i += gridDim.x * blockDim.x) c[i] = 0;
}
__global__ void csr_hist2(const int* __restrict__ e0, int E0,
                          const int* __restrict__ e1, int E1)
{
    const int total = E0 + E1;
    for (int i = blockIdx.x * blockDim.x + threadIdx.x; i < total;
         i += gridDim.x * blockDim.x) {
        if (i < E0) atomicAdd(&g_cnt[0][e0[2 * i]], 1);
        else        atomicAdd(&g_cnt[1][e1[2 * (i - E0)]], 1);
    }
}
__global__ void csr_scan1()
{
    const int s = blockIdx.y;
    __shared__ int sh[SCAN_BLK];
    const int t = threadIdx.x;
    const int idx = blockIdx.x * SCAN_BLK + t;
    int v = (idx < NMAX) ? g_cnt[s][idx] : 0;
    sh[t] = v; __syncthreads();
    #pragma unroll
    for (int d = 1; d < SCAN_BLK; d <<= 1) {
        int x = (t >= d) ? sh[t - d] : 0;
        __syncthreads();
        sh[t] += x;
        __syncthreads();
    }
    if (idx < NMAX) g_off[s][idx + 1] = sh[t];
    if (t == SCAN_BLK - 1) g_bsum[s][blockIdx.x] = sh[t];
    if (idx == 0) g_off[s][0] = 0;
}
__global__ void csr_scan2both()
{
    if (threadIdx.x == 0) {
        for (int s = 0; s < 2; s++) {
            int acc = 0;
            for (int b = 0; b < SCAN_NB; b++) {
                int t = g_bsum[s][b];
                g_bsum[s][b] = acc;
                acc += t;
            }
        }
    }
}
__global__ void csr_scan3c()   // finalize offsets + write cursors
{
    const int s = blockIdx.y;
    for (int idx = blockIdx.x * blockDim.x + threadIdx.x; idx < NMAX;
         idx += gridDim.x * blockDim.x) {
        const int v = g_off[s][idx + 1] + g_bsum[s][idx >> 10];
        g_off[s][idx + 1] = v;
        if (idx + 1 < NMAX) g_cur[s][idx + 1] = v;
        if (idx == 0) g_cur[s][0] = 0;
    }
}
__global__ void csr_fill2(const int* __restrict__ e0, int E0,
                          const int* __restrict__ e1, int E1)
{
    const int total = E0 + E1;
    for (int i = blockIdx.x * blockDim.x + threadIdx.x; i < total;
         i += gridDim.x * blockDim.x) {
        const int s = (i < E0) ? 0 : 1;
        const int* e = (s == 0) ? e0 : e1;
        const int k = (s == 0) ? i : i - E0;
        const int dst = e[2 * k];
        const int src = e[2 * k + 1];
        const int slot = atomicAdd(&g_cur[s][dst], 1);
        g_srcs[s][slot] = src;
    }
}

// ---------------------------------------------------------------------------
// Fused gather over BOTH edge sets:
//   inc[v] = sum_{e in set0(v)} z0[src(e)] + sum_{e in set1(v)} z1[src(e)]
// One warp per node, register accumulation, one plain store (no read).
// ---------------------------------------------------------------------------
__global__ void gather_both(const float* __restrict__ z0,
                            const float* __restrict__ z1,
                            float* __restrict__ inc, int N)
{
    const int v = (int)((blockIdx.x * blockDim.x + threadIdx.x) >> 5);
    const int lane = threadIdx.x & 31;
    if (v >= N) return;
    float4 a0 = make_float4(0.f, 0.f, 0.f, 0.f);
    float4 a1 = a0;
    #pragma unroll
    for (int s = 0; s < 2; s++) {
        const float* z = s ? z1 : z0;
        const int st = g_off[s][v];
        const int en = g_off[s][v + 1];
        for (int i = st; i < en; i++) {
            const int src = g_srcs[s][i];
            const float4* zr = reinterpret_cast<const float4*>(z + (size_t)src * LD);
            const float4 b = zr[lane];
            a0.x += b.x; a0.y += b.y; a0.z += b.z; a0.w += b.w;
            if (lane < 8) {
                const float4 c = zr[lane + 32];
                a1.x += c.x; a1.y += c.y; a1.z += c.z; a1.w += c.w;
            }
        }
    }
    float4* ir = reinterpret_cast<float4*>(inc + (size_t)v * LD);
    ir[lane] = a0;
    if (lane < 8) ir[lane + 32] = a1;
}

__global__ void zero_f4(float4* __restrict__ p, int n4)
{
    int i = blockIdx.x * blockDim.x + threadIdx.x;
    const int stride = gridDim.x * blockDim.x;
    for (; i < n4; i += stride) p[i] = make_float4(0.f, 0.f, 0.f, 0.f);
}

__global__ void init_h(const float* __restrict__ nodes,
                       float* __restrict__ h, int N)
{
    int idx = blockIdx.x * blockDim.x + threadIdx.x;
    const int total = N * LD;
    const int stride = gridDim.x * blockDim.x;
    for (; idx < total; idx += stride) {
        const int r = idx / LD, c = idx - r * LD;
        h[idx] = (c < HD) ? nodes[r * HD + c] : 0.f;
    }
}

// GRU gate combine, float4-vectorized: h = (1-z)*tanh(in + r*hn) + z*h.
// Pads: all gate pads are 0 -> h pad stays 0 (0.5*0 + 0.5*0).
__global__ void gru_gate4(const float* __restrict__ gates,
                          float* __restrict__ h, int N)
{
    const int n4 = N * (LD / 4);
    const float4* gir = reinterpret_cast<const float4*>(gates + 0 * GS);
    const float4* giz = reinterpret_cast<const float4*>(gates + 1 * GS);
    const float4* gin = reinterpret_cast<const float4*>(gates + 2 * GS);
    const float4* ghr = reinterpret_cast<const float4*>(gates + 3 * GS);
    const float4* ghz = reinterpret_cast<const float4*>(gates + 4 * GS);
    const float4* ghn = reinterpret_cast<const float4*>(gates + 5 * GS);
    float4* hp = reinterpret_cast<float4*>(h);
    int idx = blockIdx.x * blockDim.x + threadIdx.x;
    const int stride = gridDim.x * blockDim.x;
    for (; idx < n4; idx += stride) {
        const float4 ir = gir[idx], iz = giz[idx], in_ = gin[idx];
        const float4 hr = ghr[idx], hz = ghz[idx], hn = ghn[idx];
        float4 ho = hp[idx];
        #pragma unroll
        for (int c = 0; c < 4; c++) {
            const float irv = (&ir.x)[c], izv = (&iz.x)[c], inv = (&in_.x)[c];
            const float hrv = (&hr.x)[c], hzv = (&hz.x)[c], hnv = (&hn.x)[c];
            const float r  = 1.f / (1.f + expf(-(irv + hrv)));
            const float zz = 1.f / (1.f + expf(-(izv + hzv)));
            const float n  = tanhf(inv + r * hnv);
            (&ho.x)[c] = (1.f - zz) * n + zz * (&ho.x)[c];
        }
        hp[idx] = ho;
    }
}

// Segment sum over sorted graph_ids.
__global__ void seg_sum(const float* __restrict__ h,
                        const int* __restrict__ gid,
                        float* __restrict__ gout, int N)
{
    const int f = threadIdx.x;
    const int r0 = blockIdx.x * 256;
    const int r1 = min(r0 + 256, N);
    float acc = 0.f;
    int cur = -1;
    for (int r = r0; r < r1; r++) {
        const int id = gid[r];
        if (id != cur) {
            if (cur >= 0 && f < HD) atomicAdd(&gout[cur * HD + f], acc);
            acc = 0.f; cur = id;
        }
        if (f < HD) acc += h[(size_t)r * LD + f];
    }
    if (cur >= 0 && f < HD) atomicAdd(&gout[cur * HD + f], acc);
}

// Head MLP (16 rows): one block.
__global__ void mlp_head(const float* __restrict__ gg,
                         const float* __restrict__ ptype,
                         const float* __restrict__ fc1W, const float* __restrict__ fc1b,
                         const float* __restrict__ fc2W, const float* __restrict__ fc2b,
                         const float* __restrict__ fcLW, const float* __restrict__ fcLb,
                         float* __restrict__ out)
{
    __shared__ float sx [GMAX * 151];
    __shared__ float sy1[GMAX * 80];
    __shared__ float sy2[GMAX * 80];
    const int tid = threadIdx.x;

    for (int p = tid; p < GMAX * HD; p += blockDim.x) {
        const int g = p / HD, k = p - g * HD;
        float lg = logf(gg[p]);
        if (isnan(lg)) lg = 0.f;
        sx[g * 151 + k] = fmaxf(lg, 0.f);
    }
    for (int p = tid; p < GMAX; p += blockDim.x) sx[p * 151 + 150] = ptype[p];
    __syncthreads();

    for (int p = tid; p < GMAX * 80; p += blockDim.x) {
        const int g = p / 80, o = p - g * 80;
        float s = fc1b[o];
        for (int k = 0; k < 151; k++) s += fc1W[o * 151 + k] * sx[g * 151 + k];
        sy1[g * 80 + o] = s > 0.f ? s : 0.01f * s;
    }
    __syncthreads();

    for (int p = tid; p < GMAX * 80; p += blockDim.x) {
        const int g = p / 80, o = p - g * 80;
        float s = fc2b[o];
        for (int k = 0; k < 80; k++) s += fc2W[o * 80 + k] * sy1[g * 80 + k];
        sy2[g * 80 + o] = s > 0.f ? s : 0.01f * s;
    }
    __syncthreads();

    for (int p = tid; p < GMAX * 10; p += blockDim.x) {
        const int g = p / 10, o = p - g * 10;
        float s = fcLb[o];
        for (int k = 0; k < 80; k++) s += fcLW[o * 80 + k] * sy2[g * 80 + k];
        out[g * 10 + o] = s;
    }
}

// ---------------------------------------------------------------------------
extern "C" void kernel_launch(void* const* d_in, const int* in_sizes, int n_in,
                              void* d_out, int out_size)
{
    const float* nodes = (const float*)d_in[0];
    const float* ptype = (const float*)d_in[1];
    const float* W1_0  = (const float*)d_in[2];  const float* b1_0 = (const float*)d_in[3];
    const float* W2_0  = (const float*)d_in[4];  const float* b2_0 = (const float*)d_in[5];
    const float* W1_1  = (const float*)d_in[6];  const float* b1_1 = (const float*)d_in[7];
    const float* W2_1  = (const float*)d_in[8];  const float* b2_1 = (const float*)d_in[9];
    const float* Wih   = (const float*)d_in[10]; const float* bih  = (const float*)d_in[11];
    const float* Whh   = (const float*)d_in[12]; const float* bhh  = (const float*)d_in[13];
    const float* fc1W  = (const float*)d_in[14]; const float* fc1b = (const float*)d_in[15];
    const float* fc2W  = (const float*)d_in[16]; const float* fc2b = (const float*)d_in[17];
    const float* fcLW  = (const float*)d_in[18]; const float* fcLb = (const float*)d_in[19];
    const int* edges0  = (const int*)d_in[20];
    const int* edges1  = (const int*)d_in[21];
    const int* gids    = (const int*)d_in[22];

    const int N  = in_sizes[0] / HD;
    const int E0 = in_sizes[20] / 2;
    const int E1 = in_sizes[21] / 2;
    const int PASSES = 4;

    float *ph, *pt0, *pt1, *pz0, *pz1, *pinc, *pg, *pgraph;
    cudaGetSymbolAddress((void**)&ph,     g_h);
    cudaGetSymbolAddress((void**)&pt0,    g_t0);
    cudaGetSymbolAddress((void**)&pt1,    g_t1);
    cudaGetSymbolAddress((void**)&pz0,    g_z0);
    cudaGetSymbolAddress((void**)&pz1,    g_z1);
    cudaGetSymbolAddress((void**)&pinc,   g_inc);
    cudaGetSymbolAddress((void**)&pg,     g_gate);
    cudaGetSymbolAddress((void**)&pgraph, g_graph);

    cudaFuncSetAttribute(gemm_multi, cudaFuncAttributeMaxDynamicSharedMemorySize,
                         SMEM_TOTAL);

    const int tiles = (N + BM - 1) / BM;
    const int gatherBlocks = (N * 32 + 255) / 256;

    make_wsplit<<<256, 256>>>(W1_0, W2_0, W1_1, W2_1, Wih, Whh);
    init_h<<<2048, 256>>>(nodes, ph, N);

    // ---- CSR build (both edge sets, merged launches) ----
    csr_zero<<<256, 256>>>();
    csr_hist2<<<512, 256>>>(edges0, E0, edges1, E1);
    csr_scan1<<<dim3(SCAN_NB, 2), SCAN_BLK>>>();
    csr_scan2both<<<1, 32>>>();
    csr_scan3c<<<dim3(128, 2), 256>>>();
    csr_fill2<<<512, 256>>>(edges0, E0, edges1, E1);

    // ---- job tables ----
    Jobs L1 = {};      // t0 = lrelu(h W1_0^T + b1_0), t1 = lrelu(h W1_1^T + b1_1)
    L1.A[0] = ph;  L1.C[0] = pt0; L1.bias[0] = b1_0; L1.mat[0] = 0;
    L1.A[1] = ph;  L1.C[1] = pt1; L1.bias[1] = b1_1; L1.mat[1] = 2;
    L1.nmats = 2;  L1.act = 1;

    Jobs L2 = {};      // z0 = t0 W2_0^T, z1 = t1 W2_1^T, gh = h Whh^T (3 gates)
    L2.A[0] = pt0; L2.C[0] = pz0;          L2.bias[0] = b2_0;     L2.mat[0] = 1;
    L2.A[1] = pt1; L2.C[1] = pz1;          L2.bias[1] = b2_1;     L2.mat[1] = 3;
    L2.A[2] = ph;  L2.C[2] = pg + 3 * GS;  L2.bias[2] = bhh;      L2.mat[2] = 7;
    L2.A[3] = ph;  L2.C[3] = pg + 4 * GS;  L2.bias[3] = bhh + HD; L2.mat[3] = 8;
    L2.A[4] = ph;  L2.C[4] = pg + 5 * GS;  L2.bias[4] = bhh + 2 * HD; L2.mat[4] = 9;
    L2.nmats = 5;  L2.act = 0;

    Jobs L4 = {};      // gi = inc Wih^T (3 gates)
    L4.A[0] = pinc; L4.C[0] = pg + 0 * GS; L4.bias[0] = bih;          L4.mat[0] = 4;
    L4.A[1] = pinc; L4.C[1] = pg + 1 * GS; L4.bias[1] = bih + HD;     L4.mat[1] = 5;
    L4.A[2] = pinc; L4.C[2] = pg + 2 * GS; L4.bias[2] = bih + 2 * HD; L4.mat[2] = 6;
    L4.nmats = 3;  L4.act = 0;

    for (int p = 0; p < PASSES; p++) {
        gemm_multi<<<148, 256, SMEM_TOTAL>>>(L1, tiles, N);
        gemm_multi<<<148, 256, SMEM_TOTAL>>>(L2, tiles, N);
        gather_both<<<gatherBlocks, 256>>>(pz0, pz1, pinc, N);
        gemm_multi<<<148, 256, SMEM_TOTAL>>>(L4, tiles, N);
        gru_gate4<<<2048, 256>>>(pg, ph, N);
    }

    zero_f4<<<16, 256>>>((float4*)pgraph, GMAX * HD / 4);
    seg_sum<<<(N + 255) / 256, 160>>>(ph, gids, pgraph, N);
    mlp_head<<<1, 256>>>(pgraph, ptype, fc1W, fc1b, fc2W, fc2b, fcLW, fcLb,
                         (float*)d_out);
}